// round 5
// baseline (speedup 1.0000x reference)
#include <cuda_runtime.h>
#include <math.h>

// Problem constants: B=32, T=1024, D=256, H=256
#define BB 32
#define TT 1024
#define DD 256
#define HH 256
#define NPART 128
#define GRID 148
#define NTHREADS 256

// Scratch (device globals — no allocation allowed)
__device__ __align__(16) float g_partial[BB * NPART * DD];   // 4 MB
__device__ __align__(16) float g_W[BB * DD];
__device__ __align__(16) float g_bias[BB * DD];
__device__ unsigned g_bar_count = 0;   // returns to 0 after every barrier
__device__ unsigned g_bar_gen   = 0;   // monotonic generation; replay-safe

// ---------------------------------------------------------------------------
// Software grid barrier. Safe because grid (148) <= SM count (152) and the
// CTA footprint (256 thr, 2KB smem) guarantees all CTAs are co-resident.
// Generation-based: works for any starting g_bar_gen value -> graph replays OK.
// ---------------------------------------------------------------------------
__device__ __forceinline__ void grid_barrier() {
    __syncthreads();
    if (threadIdx.x == 0) {
        __threadfence();
        unsigned gv = atomicAdd(&g_bar_gen, 0u);   // read gen BEFORE arriving
        if (atomicAdd(&g_bar_count, 1u) == (unsigned)gridDim.x - 1u) {
            g_bar_count = 0;                        // all arrived; safe to reset
            __threadfence();
            atomicAdd(&g_bar_gen, 1u);              // release
        } else {
            while (atomicAdd(&g_bar_gen, 0u) == gv) { __nanosleep(64); }
        }
    }
    __syncthreads();
}

__device__ __forceinline__ float gelu_exact(float v) {
    return 0.5f * v * (1.0f + erff(v * 0.70710678118654752f));
}
__device__ __forceinline__ float dot4(float4 a, float4 b) {
    return fmaf(a.x, b.x, fmaf(a.y, b.y, fmaf(a.z, b.z, a.w * b.w)));
}

// ---------------------------------------------------------------------------
// Single persistent kernel: reduce -> (mlp || zero-fill) -> apply
// ---------------------------------------------------------------------------
__global__ __launch_bounds__(NTHREADS) void fused_kernel(
        const float4* __restrict__ x4,
        const int* __restrict__ len,
        const float* __restrict__ w1w, const float* __restrict__ w1b,
        const float* __restrict__ w2w, const float* __restrict__ w2b,
        const float* __restrict__ q1w, const float* __restrict__ q1b,
        const float* __restrict__ q2w, const float* __restrict__ q2b,
        float4* __restrict__ out4) {
    __shared__ __align__(16) float c_sh[DD];
    __shared__ __align__(16) float h_sh[HH];

    const int tid = threadIdx.x;
    const int d4  = tid & 63;
    const int lt  = tid >> 6;    // 0..3

    // ---------- Phase 1: partial sums of x over T ----------
    // 1024 tiles of 32 rows; thread sums 8 rows strided by 4 (8 loads in flight)
    for (int tile = blockIdx.x; tile < BB * 32; tile += GRID) {
        int b = tile >> 5, s = tile & 31;
        size_t base = ((size_t)b * TT + (size_t)s * 32 + lt) * 64 + d4;
        float4 acc = make_float4(0.f, 0.f, 0.f, 0.f);
#pragma unroll
        for (int i = 0; i < 8; i++) {
            float4 v = x4[base + (size_t)i * 256];
            acc.x += v.x; acc.y += v.y; acc.z += v.z; acc.w += v.w;
        }
        reinterpret_cast<float4*>(g_partial)[((size_t)b * NPART + (s * 4 + lt)) * 64 + d4] = acc;
    }
    grid_barrier();

    // ---------- Phase 2: MLPs (blocks 0..63)  ||  zero-fill t>=L (blocks 64..147) ----------
    if (blockIdx.x < 2 * BB) {
        int b = blockIdx.x >> 1;
        int branch = blockIdx.x & 1;
        const float* m1w = branch ? q1w : w1w;
        const float* m1b = branch ? q1b : w1b;
        const float* m2w = branch ? q2w : w2w;
        const float* m2b = branch ? q2b : w2b;
        float* gout = branch ? g_bias : g_W;

        // reduce 128 partials -> c (coalesced over tid)
        {
            float s = 0.0f;
#pragma unroll 16
            for (int p = 0; p < NPART; p++)
                s += g_partial[((size_t)b * NPART + p) * DD + tid];
            c_sh[tid] = s / (float)len[b];
        }
        __syncthreads();

        int w = tid >> 5, lane = tid & 31;
        const float4* c4 = reinterpret_cast<const float4*>(c_sh);
        const float4* h4 = reinterpret_cast<const float4*>(h_sh);

#pragma unroll 8
        for (int jj = 0; jj < 32; jj++) {
            int o = w * 32 + jj;
            const float4* row = reinterpret_cast<const float4*>(m1w + (size_t)o * DD);
            float acc = dot4(c4[lane], row[lane]) + dot4(c4[lane + 32], row[lane + 32]);
#pragma unroll
            for (int off = 16; off > 0; off >>= 1)
                acc += __shfl_down_sync(0xFFFFFFFFu, acc, off);
            if (lane == 0) h_sh[o] = gelu_exact(acc + m1b[o]);
        }
        __syncthreads();
#pragma unroll 8
        for (int jj = 0; jj < 32; jj++) {
            int o = w * 32 + jj;
            const float4* row = reinterpret_cast<const float4*>(m2w + (size_t)o * HH);
            float acc = dot4(h4[lane], row[lane]) + dot4(h4[lane + 32], row[lane + 32]);
#pragma unroll
            for (int off = 16; off > 0; off >>= 1)
                acc += __shfl_down_sync(0xFFFFFFFFu, acc, off);
            if (lane == 0) gout[b * DD + o] = acc + m2b[o];
        }
    } else {
        // zero-fill out rows with t >= L (independent of MLP result)
        const float4 zero = make_float4(0.f, 0.f, 0.f, 0.f);
        for (int tile = (int)blockIdx.x - 2 * BB; tile < 2048; tile += GRID - 2 * BB) {
            size_t base = (size_t)tile * 1024;        // 16 rows per tile
            int b = (int)(base >> 16);
            int L = __ldg(&len[b]);
            int tbase = (int)((base >> 6) & 1023);
            if (tbase + 16 <= L) continue;            // whole tile valid -> phase 3
#pragma unroll
            for (int k = 0; k < 4; k++) {
                int t = tbase + k * 4 + lt;
                if (t >= L) __stcs(&out4[base + tid + (size_t)k * 256], zero);
            }
        }
    }
    grid_barrier();

    // ---------- Phase 3: apply for t < L ----------
    const float4* gW4 = reinterpret_cast<const float4*>(g_W);
    const float4* gB4 = reinterpret_cast<const float4*>(g_bias);
    for (int tile = blockIdx.x; tile < 2048; tile += GRID) {
        size_t base = (size_t)tile * 1024;
        int b = (int)(base >> 16);
        int L = __ldg(&len[b]);
        int tbase = (int)((base >> 6) & 1023);
        if (tbase >= L) continue;                     // whole tile was zero-filled
        float4 wv = gW4[b * 64 + d4];
#pragma unroll
        for (int k = 0; k < 4; k++) {
            int t = tbase + k * 4 + lt;
            if (t < L) {
                size_t i = base + tid + (size_t)k * 256;
                float4 xv = x4[i];
                float4 o;
                o.x = fmaf(xv.x, wv.x, xv.x);
                o.y = fmaf(xv.y, wv.y, xv.y);
                o.z = fmaf(xv.z, wv.z, xv.z);
                o.w = fmaf(xv.w, wv.w, xv.w);
                if (t == 0) {
                    float4 bv = gB4[b * 64 + d4];
                    o.x += bv.x; o.y += bv.y; o.z += bv.z; o.w += bv.w;
                }
                __stcs(&out4[i], o);
            }
        }
    }
}

// ---------------------------------------------------------------------------
extern "C" void kernel_launch(void* const* d_in, const int* in_sizes, int n_in,
                              void* d_out, int out_size) {
    const float* x     = (const float*)d_in[0];
    const int*   len_x = (const int*)d_in[1];
    const float* Ww1_w = (const float*)d_in[2];
    const float* Ww1_b = (const float*)d_in[3];
    const float* Ww2_w = (const float*)d_in[4];
    const float* Ww2_b = (const float*)d_in[5];
    const float* Wb1_w = (const float*)d_in[6];
    const float* Wb1_b = (const float*)d_in[7];
    const float* Wb2_w = (const float*)d_in[8];
    const float* Wb2_b = (const float*)d_in[9];
    float* out = (float*)d_out;

    fused_kernel<<<GRID, NTHREADS>>>(
        reinterpret_cast<const float4*>(x), len_x,
        Ww1_w, Ww1_b, Ww2_w, Ww2_b,
        Wb1_w, Wb1_b, Wb2_w, Wb2_b,
        reinterpret_cast<float4*>(out));
}

// round 6
// speedup vs baseline: 1.1291x; 1.1291x over previous
#include <cuda_runtime.h>
#include <math.h>

// Problem constants: B=32, T=1024, D=256, H=256
#define BB 32
#define TT 1024
#define DD 256
#define HH 256
#define NPART 128
#define GRID 740            // 5 CTAs per SM on 148 SMs -> all co-resident
#define NTHREADS 256

// Scratch (device globals — no allocation allowed)
__device__ __align__(16) float g_partial[BB * NPART * DD];   // 4 MB
__device__ __align__(16) float g_W[BB * DD];
__device__ __align__(16) float g_bias[BB * DD];
__device__ unsigned g_bar_count = 0;   // returns to 0 after every barrier
__device__ unsigned g_bar_gen   = 0;   // monotonic generation; replay-safe

// ---------------------------------------------------------------------------
// Software grid barrier. Safe: 740 CTAs of (<=40 regs, 256 thr, 2KB smem)
// -> occupancy limit 6/SM, so all 740 (5/SM) are wave-1 co-resident.
// Generation-based: correct for any starting gen value -> graph replays OK.
// ---------------------------------------------------------------------------
__device__ __forceinline__ void grid_barrier() {
    __syncthreads();
    if (threadIdx.x == 0) {
        __threadfence();
        unsigned gv = atomicAdd(&g_bar_gen, 0u);   // read gen BEFORE arriving
        if (atomicAdd(&g_bar_count, 1u) == (unsigned)gridDim.x - 1u) {
            g_bar_count = 0;                        // all arrived; safe to reset
            __threadfence();
            atomicAdd(&g_bar_gen, 1u);              // release
        } else {
            while (atomicAdd(&g_bar_gen, 0u) == gv) { __nanosleep(32); }
        }
    }
    __syncthreads();
}

__device__ __forceinline__ float gelu_exact(float v) {
    return 0.5f * v * (1.0f + erff(v * 0.70710678118654752f));
}
__device__ __forceinline__ float dot4(float4 a, float4 b) {
    return fmaf(a.x, b.x, fmaf(a.y, b.y, fmaf(a.z, b.z, a.w * b.w)));
}

// ---------------------------------------------------------------------------
// Single persistent kernel: reduce -> (mlp || zero-fill) -> apply
// ---------------------------------------------------------------------------
__global__ __launch_bounds__(NTHREADS, 6) void fused_kernel(
        const float4* __restrict__ x4,
        const int* __restrict__ len,
        const float* __restrict__ w1w, const float* __restrict__ w1b,
        const float* __restrict__ w2w, const float* __restrict__ w2b,
        const float* __restrict__ q1w, const float* __restrict__ q1b,
        const float* __restrict__ q2w, const float* __restrict__ q2b,
        float4* __restrict__ out4) {
    __shared__ __align__(16) float c_sh[DD];
    __shared__ __align__(16) float h_sh[HH];

    const int tid = threadIdx.x;
    const int d4  = tid & 63;
    const int lt  = tid >> 6;    // 0..3

    // ---------- Phase 1: partial sums of x over T ----------
    // 1024 tiles of 32 rows; thread sums 8 rows strided by 4 (8 loads in flight)
    for (int tile = blockIdx.x; tile < BB * 32; tile += GRID) {
        int b = tile >> 5, s = tile & 31;
        size_t base = ((size_t)b * TT + (size_t)s * 32 + lt) * 64 + d4;
        float4 acc = make_float4(0.f, 0.f, 0.f, 0.f);
#pragma unroll
        for (int i = 0; i < 8; i++) {
            float4 v = x4[base + (size_t)i * 256];
            acc.x += v.x; acc.y += v.y; acc.z += v.z; acc.w += v.w;
        }
        reinterpret_cast<float4*>(g_partial)[((size_t)b * NPART + (s * 4 + lt)) * 64 + d4] = acc;
    }
    grid_barrier();

    // ---------- Phase 2: MLPs (blocks 0..63)  ||  zero-fill t>=L (rest) ----------
    if (blockIdx.x < 2 * BB) {
        int b = blockIdx.x >> 1;
        int branch = blockIdx.x & 1;
        const float* m1w = branch ? q1w : w1w;
        const float* m1b = branch ? q1b : w1b;
        const float* m2w = branch ? q2w : w2w;
        const float* m2b = branch ? q2b : w2b;
        float* gout = branch ? g_bias : g_W;

        // reduce 128 partials -> c (coalesced over tid)
        {
            float s = 0.0f;
#pragma unroll 16
            for (int p = 0; p < NPART; p++)
                s += g_partial[((size_t)b * NPART + p) * DD + tid];
            c_sh[tid] = s / (float)len[b];
        }
        __syncthreads();

        int w = tid >> 5, lane = tid & 31;
        const float4* c4 = reinterpret_cast<const float4*>(c_sh);
        const float4* h4 = reinterpret_cast<const float4*>(h_sh);

#pragma unroll 8
        for (int jj = 0; jj < 32; jj++) {
            int o = w * 32 + jj;
            const float4* row = reinterpret_cast<const float4*>(m1w + (size_t)o * DD);
            float acc = dot4(c4[lane], row[lane]) + dot4(c4[lane + 32], row[lane + 32]);
#pragma unroll
            for (int off = 16; off > 0; off >>= 1)
                acc += __shfl_down_sync(0xFFFFFFFFu, acc, off);
            if (lane == 0) h_sh[o] = gelu_exact(acc + m1b[o]);
        }
        __syncthreads();
#pragma unroll 8
        for (int jj = 0; jj < 32; jj++) {
            int o = w * 32 + jj;
            const float4* row = reinterpret_cast<const float4*>(m2w + (size_t)o * HH);
            float acc = dot4(h4[lane], row[lane]) + dot4(h4[lane + 32], row[lane + 32]);
#pragma unroll
            for (int off = 16; off > 0; off >>= 1)
                acc += __shfl_down_sync(0xFFFFFFFFu, acc, off);
            if (lane == 0) gout[b * DD + o] = acc + m2b[o];
        }
    } else {
        // zero-fill out rows with t >= L (independent of MLP result)
        const float4 zero = make_float4(0.f, 0.f, 0.f, 0.f);
        for (int tile = (int)blockIdx.x - 2 * BB; tile < 2048; tile += GRID - 2 * BB) {
            size_t base = (size_t)tile * 1024;        // 16 rows per tile
            int b = (int)(base >> 16);
            int L = __ldg(&len[b]);
            int tbase = (int)((base >> 6) & 1023);
            if (tbase + 16 <= L) continue;            // whole tile valid -> phase 3
#pragma unroll
            for (int k = 0; k < 4; k++) {
                int t = tbase + k * 4 + lt;
                if (t >= L) __stcs(&out4[base + tid + (size_t)k * 256], zero);
            }
        }
    }
    grid_barrier();

    // ---------- Phase 3: apply for t < L ----------
    const float4* gW4 = reinterpret_cast<const float4*>(g_W);
    const float4* gB4 = reinterpret_cast<const float4*>(g_bias);
    for (int tile = blockIdx.x; tile < 2048; tile += GRID) {
        size_t base = (size_t)tile * 1024;
        int b = (int)(base >> 16);
        int L = __ldg(&len[b]);
        int tbase = (int)((base >> 6) & 1023);
        if (tbase >= L) continue;                     // whole tile was zero-filled
        float4 wv = gW4[b * 64 + d4];
#pragma unroll
        for (int k = 0; k < 4; k++) {
            int t = tbase + k * 4 + lt;
            if (t < L) {
                size_t i = base + tid + (size_t)k * 256;
                float4 xv = x4[i];
                float4 o;
                o.x = fmaf(xv.x, wv.x, xv.x);
                o.y = fmaf(xv.y, wv.y, xv.y);
                o.z = fmaf(xv.z, wv.z, xv.z);
                o.w = fmaf(xv.w, wv.w, xv.w);
                if (t == 0) {
                    float4 bv = gB4[b * 64 + d4];
                    o.x += bv.x; o.y += bv.y; o.z += bv.z; o.w += bv.w;
                }
                __stcs(&out4[i], o);
            }
        }
    }
}

// ---------------------------------------------------------------------------
extern "C" void kernel_launch(void* const* d_in, const int* in_sizes, int n_in,
                              void* d_out, int out_size) {
    const float* x     = (const float*)d_in[0];
    const int*   len_x = (const int*)d_in[1];
    const float* Ww1_w = (const float*)d_in[2];
    const float* Ww1_b = (const float*)d_in[3];
    const float* Ww2_w = (const float*)d_in[4];
    const float* Ww2_b = (const float*)d_in[5];
    const float* Wb1_w = (const float*)d_in[6];
    const float* Wb1_b = (const float*)d_in[7];
    const float* Wb2_w = (const float*)d_in[8];
    const float* Wb2_b = (const float*)d_in[9];
    float* out = (float*)d_out;

    fused_kernel<<<GRID, NTHREADS>>>(
        reinterpret_cast<const float4*>(x), len_x,
        Ww1_w, Ww1_b, Ww2_w, Ww2_b,
        Wb1_w, Wb1_b, Wb2_w, Wb2_b,
        reinterpret_cast<float4*>(out));
}

// round 7
// speedup vs baseline: 1.1728x; 1.0387x over previous
#include <cuda_runtime.h>
#include <math.h>

// Problem constants: B=32, T=1024, D=256, H=256
#define BB 32
#define TT 1024
#define DD 256
#define HH 256
#define NPART 64             // partials per batch after in-CTA reduce
#define GRID 740             // 5 CTAs/SM on 148 SMs -> all co-resident (occ lim 6)
#define NTHREADS 256

// Scratch (device globals — no allocation allowed)
__device__ __align__(16) float g_partial[BB * NPART * DD];   // 2 MB
__device__ __align__(16) float g_W[BB * DD];
__device__ __align__(16) float g_bias[BB * DD];
__device__ unsigned g_ticket = 0;            // monotonic arrival tickets
__device__ volatile unsigned g_gen = 0;      // monotonic generation

// ---------------------------------------------------------------------------
// Grid barrier, ticket-based, poll via plain volatile LOADS (no atomic spin —
// the LTS atomic ALU serializes per-address; atomic polling was costing ~10us).
// Never resets -> no reset race; replay-safe (each launch consumes 2*GRID
// tickets and +2 generations; code only uses relative values).
// Safe only because all GRID CTAs are co-resident (GRID = 5/SM, occ limit 6).
// ---------------------------------------------------------------------------
__device__ __forceinline__ void grid_barrier() {
    __syncthreads();
    if (threadIdx.x == 0) {
        __threadfence();
        unsigned gv = g_gen;                          // volatile read (fresh)
        unsigned t = atomicAdd(&g_ticket, 1u);
        if ((t % GRID) == GRID - 1u) {
            __threadfence();
            g_gen = gv + 1u;                          // release
        } else {
            while (g_gen == gv) { __nanosleep(32); }  // plain-load spin
        }
        __threadfence();
    }
    __syncthreads();
}

__device__ __forceinline__ float gelu_exact(float v) {
    return 0.5f * v * (1.0f + erff(v * 0.70710678118654752f));
}
__device__ __forceinline__ float dot4(float4 a, float4 b) {
    return fmaf(a.x, b.x, fmaf(a.y, b.y, fmaf(a.z, b.z, a.w * b.w)));
}

// ---------------------------------------------------------------------------
// Single persistent kernel: reduce -> (mlp || zero-fill) -> apply
// ---------------------------------------------------------------------------
__global__ __launch_bounds__(NTHREADS, 6) void fused_kernel(
        const float4* __restrict__ x4,
        const int* __restrict__ len,
        const float* __restrict__ w1w, const float* __restrict__ w1b,
        const float* __restrict__ w2w, const float* __restrict__ w2b,
        const float* __restrict__ q1w, const float* __restrict__ q1b,
        const float* __restrict__ q2w, const float* __restrict__ q2b,
        float4* __restrict__ out4) {
    __shared__ __align__(16) float4 red_sh[4][64];    // 4 KB
    __shared__ __align__(16) float c_sh[DD];
    __shared__ __align__(16) float h_sh[HH];

    const int tid = threadIdx.x;
    const int d4  = tid & 63;
    const int lt  = tid >> 6;    // 0..3

    // ---------- Phase 1: partial sums of x over T ----------
    // 2048 tiles of 16 rows; thread sums rows {lt, lt+4, lt+8, lt+12} of the
    // tile (4 independent loads); in-CTA smem reduce 4 -> 1 partial per tile.
    for (int tile = blockIdx.x; tile < 2048; tile += GRID) {
        int b = tile >> 6, s = tile & 63;             // 64 tiles per batch
        size_t base = ((size_t)b * TT + (size_t)s * 16 + lt) * 64 + d4;
        float4 acc = make_float4(0.f, 0.f, 0.f, 0.f);
#pragma unroll
        for (int i = 0; i < 4; i++) {
            float4 v = x4[base + (size_t)i * 4 * 64];
            acc.x += v.x; acc.y += v.y; acc.z += v.z; acc.w += v.w;
        }
        red_sh[lt][d4] = acc;
        __syncthreads();
        if (lt == 0) {
            float4 a = red_sh[0][d4], v1 = red_sh[1][d4],
                   v2 = red_sh[2][d4], v3 = red_sh[3][d4];
            a.x += v1.x + v2.x + v3.x;
            a.y += v1.y + v2.y + v3.y;
            a.z += v1.z + v2.z + v3.z;
            a.w += v1.w + v2.w + v3.w;
            reinterpret_cast<float4*>(g_partial)[((size_t)b * NPART + s) * 64 + d4] = a;
        }
        __syncthreads();
    }
    grid_barrier();

    // ---------- Phase 2: MLPs (blocks 0..63)  ||  zero-fill t>=L (rest) ----------
    if (blockIdx.x < 2 * BB) {
        int b = blockIdx.x >> 1;
        int branch = blockIdx.x & 1;
        const float* m1w = branch ? q1w : w1w;
        const float* m1b = branch ? q1b : w1b;
        const float* m2w = branch ? q2w : w2w;
        const float* m2b = branch ? q2b : w2b;
        float* gout = branch ? g_bias : g_W;

        // reduce 64 partials -> c (coalesced over tid)
        {
            float s = 0.0f;
#pragma unroll 16
            for (int p = 0; p < NPART; p++)
                s += g_partial[((size_t)b * NPART + p) * DD + tid];
            c_sh[tid] = s / (float)len[b];
        }
        __syncthreads();

        int w = tid >> 5, lane = tid & 31;
        const float4* c4 = reinterpret_cast<const float4*>(c_sh);
        const float4* h4 = reinterpret_cast<const float4*>(h_sh);

#pragma unroll 8
        for (int jj = 0; jj < 32; jj++) {
            int o = w * 32 + jj;
            const float4* row = reinterpret_cast<const float4*>(m1w + (size_t)o * DD);
            float acc = dot4(c4[lane], row[lane]) + dot4(c4[lane + 32], row[lane + 32]);
#pragma unroll
            for (int off = 16; off > 0; off >>= 1)
                acc += __shfl_down_sync(0xFFFFFFFFu, acc, off);
            if (lane == 0) h_sh[o] = gelu_exact(acc + m1b[o]);
        }
        __syncthreads();
#pragma unroll 8
        for (int jj = 0; jj < 32; jj++) {
            int o = w * 32 + jj;
            const float4* row = reinterpret_cast<const float4*>(m2w + (size_t)o * HH);
            float acc = dot4(h4[lane], row[lane]) + dot4(h4[lane + 32], row[lane + 32]);
#pragma unroll
            for (int off = 16; off > 0; off >>= 1)
                acc += __shfl_down_sync(0xFFFFFFFFu, acc, off);
            if (lane == 0) gout[b * DD + o] = acc + m2b[o];
        }
    } else {
        // zero-fill out rows with t >= L (independent of MLP result)
        const float4 zero = make_float4(0.f, 0.f, 0.f, 0.f);
        for (int tile = (int)blockIdx.x - 2 * BB; tile < 2048; tile += GRID - 2 * BB) {
            size_t base = (size_t)tile * 1024;        // 16 rows per tile
            int b = (int)(base >> 16);
            int L = __ldg(&len[b]);
            int tbase = (int)((base >> 6) & 1023);
            if (tbase + 16 <= L) continue;            // whole tile valid -> phase 3
#pragma unroll
            for (int k = 0; k < 4; k++) {
                int t = tbase + k * 4 + lt;
                if (t >= L) __stcs(&out4[base + tid + (size_t)k * 256], zero);
            }
        }
    }
    grid_barrier();

    // ---------- Phase 3: apply for t < L ----------
    const float4* gW4 = reinterpret_cast<const float4*>(g_W);
    const float4* gB4 = reinterpret_cast<const float4*>(g_bias);
    for (int tile = blockIdx.x; tile < 2048; tile += GRID) {
        size_t base = (size_t)tile * 1024;
        int b = (int)(base >> 16);
        int L = __ldg(&len[b]);
        int tbase = (int)((base >> 6) & 1023);
        if (tbase >= L) continue;                     // whole tile was zero-filled
        float4 wv = gW4[b * 64 + d4];
#pragma unroll
        for (int k = 0; k < 4; k++) {
            int t = tbase + k * 4 + lt;
            if (t < L) {
                size_t i = base + tid + (size_t)k * 256;
                float4 xv = x4[i];
                float4 o;
                o.x = fmaf(xv.x, wv.x, xv.x);
                o.y = fmaf(xv.y, wv.y, xv.y);
                o.z = fmaf(xv.z, wv.z, xv.z);
                o.w = fmaf(xv.w, wv.w, xv.w);
                if (t == 0) {
                    float4 bv = gB4[b * 64 + d4];
                    o.x += bv.x; o.y += bv.y; o.z += bv.z; o.w += bv.w;
                }
                __stcs(&out4[i], o);
            }
        }
    }
}

// ---------------------------------------------------------------------------
extern "C" void kernel_launch(void* const* d_in, const int* in_sizes, int n_in,
                              void* d_out, int out_size) {
    const float* x     = (const float*)d_in[0];
    const int*   len_x = (const int*)d_in[1];
    const float* Ww1_w = (const float*)d_in[2];
    const float* Ww1_b = (const float*)d_in[3];
    const float* Ww2_w = (const float*)d_in[4];
    const float* Ww2_b = (const float*)d_in[5];
    const float* Wb1_w = (const float*)d_in[6];
    const float* Wb1_b = (const float*)d_in[7];
    const float* Wb2_w = (const float*)d_in[8];
    const float* Wb2_b = (const float*)d_in[9];
    float* out = (float*)d_out;

    fused_kernel<<<GRID, NTHREADS>>>(
        reinterpret_cast<const float4*>(x), len_x,
        Ww1_w, Ww1_b, Ww2_w, Ww2_b,
        Wb1_w, Wb1_b, Wb2_w, Wb2_b,
        reinterpret_cast<float4*>(out));
}